// round 15
// baseline (speedup 1.0000x reference)
#include <cuda_runtime.h>
#include <cstdint>

#define B 4
#define L 2048
#define H 8
#define D 64
#define NT 38           // n_top
#define SK 38           // sample_k
#define CH 32           // cumsum chunks
#define CROWS (L/CH)    // 64 rows per chunk
#define KC 64           // attention key-chunk
#define NC (L/KC)       // 32 attention chunks
#define BH (B*H)

// ---------------- scratch (no allocations allowed) ----------------
__device__ float  g_M[BH*L];            // sparsity metric
__device__ int    g_top[BH*NT];         // selected queries per (b,h), SORTED by q
__device__ float  g_csum[BH*CH*D];      // per-chunk column sums
__device__ float  g_pl[BH*NT*NC];       // attention partial sum(exp)
__device__ float  g_pacc[BH*NT*NC*D];   // attention partial sum(exp*V)

// ---------------- threefry2x32-20 (jax partitionable path) ----------------
__device__ __forceinline__ uint32_t rotl32(uint32_t x, int r) {
    return (x << r) | (x >> (32 - r));
}

__device__ __forceinline__ void threefry2x32(uint32_t k0, uint32_t k1,
                                             uint32_t x0, uint32_t x1,
                                             uint32_t& o0, uint32_t& o1) {
    uint32_t ks2 = k0 ^ k1 ^ 0x1BD11BDAu;
    x0 += k0; x1 += k1;
#define TF_R(R) { x0 += x1; x1 = rotl32(x1, (R)); x1 ^= x0; }
    TF_R(13) TF_R(15) TF_R(26) TF_R(6)
    x0 += k1;  x1 += ks2 + 1u;
    TF_R(17) TF_R(29) TF_R(16) TF_R(24)
    x0 += ks2; x1 += k0 + 2u;
    TF_R(13) TF_R(15) TF_R(26) TF_R(6)
    x0 += k0;  x1 += k1 + 3u;
    TF_R(17) TF_R(29) TF_R(16) TF_R(24)
    x0 += k1;  x1 += ks2 + 4u;
    TF_R(13) TF_R(15) TF_R(26) TF_R(6)
    x0 += ks2; x1 += k0 + 5u;
#undef TF_R
    o0 = x0; o1 = x1;
}

// index for sample (q, j): threefry(lower_key, 0, q*SK+j); bits = o0^o1; & 2047
__device__ __forceinline__ int sample_idx(uint32_t c0, uint32_t c1, int q, int j) {
    uint32_t o0, o1;
    threefry2x32(c0, c1, 0u, (uint32_t)(q * SK + j), o0, o1);
    return (int)((o0 ^ o1) & (uint32_t)(L - 1));
}

// ---------------- fused launch 1: k_M (inline threefry) + csum_partial ---------
__global__ void k_fused_M_csum(const float* __restrict__ Q, const float* __restrict__ K,
                               const float* __restrict__ V) {
    int bx = blockIdx.x;
    int tid = threadIdx.x;
    if (bx < 8192) {
        int bh = bx >> 8;
        int b = bh >> 3, h = bh & 7;
        int w = tid >> 5, l = tid & 31;
        int q = (bx & 255) * 8 + w;
        int s = l >> 3, c = l & 7;

        // lower key (constant-folds)
        uint32_t c0, c1;
        threefry2x32(0u, 42u, 0u, 1u, c0, c1);
        // lane l holds idx for j=l; lanes also compute j=l+32 (valid for l<6)
        int idx_lo = sample_idx(c0, c1, q, l);
        int idx_hi = sample_idx(c0, c1, q, min(l + 32, SK - 1));

        const float4* qr = (const float4*)(Q + (((size_t)b * L + q) * H + h) * D);
        float4 qa = qr[2 * c], qb = qr[2 * c + 1];
        const float4* Kb = (const float4*)(K + (((size_t)b * L) * H + h) * D);

        float mx = -1e30f, sm = 0.f;
        #pragma unroll 2
        for (int j0 = 0; j0 < 40; j0 += 4) {
            int jc = min(j0 + s, SK - 1);
            int klo = __shfl_sync(0xffffffffu, idx_lo, jc & 31);
            int khi = __shfl_sync(0xffffffffu, idx_hi, jc & 31);
            int k = (jc < 32) ? klo : khi;
            const float4* kr = Kb + (size_t)k * (H * D / 4) + 2 * c;
            float4 ka = kr[0], kb = kr[1];
            float p = ka.x * qa.x + ka.y * qa.y + ka.z * qa.z + ka.w * qa.w
                    + kb.x * qb.x + kb.y * qb.y + kb.z * qb.z + kb.w * qb.w;
            p += __shfl_xor_sync(0xffffffffu, p, 1);
            p += __shfl_xor_sync(0xffffffffu, p, 2);
            p += __shfl_xor_sync(0xffffffffu, p, 4);
            bool valid = (j0 + s < SK);
            mx = fmaxf(mx, valid ? p : -1e30f);
            sm += valid ? p : 0.f;
        }
        mx = fmaxf(mx, __shfl_xor_sync(0xffffffffu, mx, 8));
        sm += __shfl_xor_sync(0xffffffffu, sm, 8);
        mx = fmaxf(mx, __shfl_xor_sync(0xffffffffu, mx, 16));
        sm += __shfl_xor_sync(0xffffffffu, sm, 16);
        if (l == 0) g_M[bh * L + q] = mx - sm * (1.0f / (float)L);
    } else {
        int idx = bx - 8192;
        int bh = idx >> 5, chunk = idx & 31;
        int b = bh >> 3, h = bh & 7;
        int c = tid & 63, r0 = tid >> 6;
        float s = 0.f;
        for (int r = r0; r < CROWS; r += 4)
            s += V[(((size_t)b * L + chunk * CROWS + r) * H + h) * D + c];
        __shared__ float red[256];
        red[tid] = s;
        __syncthreads();
        if (tid < 64)
            g_csum[((size_t)bh * CH + chunk) * D + c] =
                red[tid] + red[tid + 64] + red[tid + 128] + red[tid + 192];
    }
}

// ---------------- fused launch 2: topk blocks + csum_scan blocks ----------------
__global__ void k_fused_topk_scan(const float* __restrict__ V, float* __restrict__ out) {
    int bx = blockIdx.x;
    int tid = threadIdx.x;
    if (bx < BH) {
        int bh = bx;
        __shared__ float vals[L];
        __shared__ float wv[8];
        __shared__ int   wi[8];
        __shared__ int   sel[NT];
        int w = tid >> 5, lane = tid & 31;
        for (int i = tid; i < L; i += 256) vals[i] = g_M[bh * L + i];
        __syncthreads();
        for (int t = 0; t < NT; t++) {
            float bv = -1e38f; int bi = L;
            #pragma unroll
            for (int rep = 0; rep < L / 256; rep++) {
                int i = tid + rep * 256;
                float v = vals[i];
                if (v > bv || (v == bv && i < bi)) { bv = v; bi = i; }
            }
            #pragma unroll
            for (int off = 16; off; off >>= 1) {
                float ov = __shfl_down_sync(0xffffffffu, bv, off);
                int   oi = __shfl_down_sync(0xffffffffu, bi, off);
                if (ov > bv || (ov == bv && oi < bi)) { bv = ov; bi = oi; }
            }
            if (lane == 0) { wv[w] = bv; wi[w] = bi; }
            __syncthreads();
            if (tid == 0) {
                float fv = wv[0]; int fi = wi[0];
                #pragma unroll
                for (int ww = 1; ww < 8; ww++)
                    if (wv[ww] > fv || (wv[ww] == fv && wi[ww] < fi)) { fv = wv[ww]; fi = wi[ww]; }
                sel[t] = fi;
                vals[fi] = -1e38f;
            }
            __syncthreads();
        }
        if (tid < NT) {
            int v = sel[tid];
            int r = 0;
            #pragma unroll
            for (int i = 0; i < NT; i++) r += (sel[i] < v);
            g_top[bh * NT + r] = v;
        }
    } else {
        int idx = bx - BH;
        int bh = idx >> 5, chunk = idx & 31;
        int b = bh >> 3, h = bh & 7;
        __shared__ float tile[CROWS * 64];
        __shared__ float gsum[4 * 64];
        __shared__ float sbase[64];
        int c = tid & 63, g = tid >> 6;   // 4 groups x 16 rows

        if (tid < 64) {
            float s = 0.f;
            for (int cc = 0; cc < chunk; cc++)
                s += g_csum[((size_t)bh * CH + cc) * D + tid];
            sbase[tid] = s;
        }
        int r0 = chunk * CROWS;
        for (int i = tid; i < CROWS * 64; i += 256) {
            int r = i >> 6, cc = i & 63;
            tile[i] = V[(((size_t)b * L + r0 + r) * H + h) * D + cc];
        }
        __syncthreads();

        float s = 0.f;
        int rb = g * 16;
        #pragma unroll
        for (int r = 0; r < 16; r++) {
            s += tile[(rb + r) * 64 + c];
            tile[(rb + r) * 64 + c] = s;
        }
        gsum[g * 64 + c] = s;
        __syncthreads();

        float prefix = sbase[c];
        for (int gg = 0; gg < g; gg++) prefix += gsum[gg * 64 + c];
        #pragma unroll
        for (int r = 0; r < 16; r++)
            out[(((size_t)b * L + r0 + rb + r) * H + h) * D + c] =
                tile[(rb + r) * 64 + c] + prefix;
    }
}

// ---------------- attention split-K: pairwise Phase A + float4 Phase B --------
__global__ void __launch_bounds__(256, 4)
k_attn_part(const float* __restrict__ Q, const float* __restrict__ K,
            const float* __restrict__ V) {
    int bh = blockIdx.x, chunk = blockIdx.y;
    int b = bh >> 3, h = bh & 7;
    int c0 = chunk * KC;
    int tid = threadIdx.x;
    int w = tid >> 5, lane = tid & 31;

    __shared__ float4 sK[KC * 16];     // swizzled
    __shared__ float4 sV[KC * 16];     // natural
    __shared__ float  sE[NT][KC];
    __shared__ int    sTop[NT];
    __shared__ int    s_lo;

    if (tid < NT) sTop[tid] = g_top[bh * NT + tid];
    __syncthreads();
    if (tid == 0) {
        int lo = NT;
        for (int i = 0; i < NT; i++)
            if (sTop[i] >= c0) { lo = i; break; }
        s_lo = lo;
    }
    __syncthreads();
    int lo = s_lo;
    if (lo >= NT) return;   // no active queries in this chunk

    const float4* K4 = (const float4*)K;
    const float4* V4 = (const float4*)V;
    for (int i = tid; i < KC * 16; i += 256) {
        int row = i >> 4, f = i & 15;
        size_t g = ((size_t)(b * L + c0 + row) * H + h) * 16 + f;
        sK[(row << 4) | (f ^ (row & 15))] = K4[g];
        sV[i] = V4[g];
    }
    __syncthreads();

    const float scale = 0.125f;
    const float4* Q4 = (const float4*)Q;
    int k0 = lane, k1 = lane + 32;

    // ---- Phase A: two queries (t0, t0+8) per K-tile sweep ----
    for (int t0 = lo + w; t0 < NT; t0 += 16) {
        int tB = t0 + 8;
        bool hasB = (tB < NT);
        int qA = sTop[t0];
        int qB = sTop[hasB ? tB : t0];
        int nkA = min(KC, qA - c0 + 1);
        int nkB = min(KC, qB - c0 + 1);
        size_t qoffA = ((size_t)(b * L + qA) * H + h) * 16;
        size_t qoffB = ((size_t)(b * L + qB) * H + h) * 16;
        float dA0 = 0.f, dA1 = 0.f, dB0 = 0.f, dB1 = 0.f;
        #pragma unroll
        for (int i = 0; i < 16; i++) {
            float4 ka = sK[(k0 << 4) | (i ^ (k0 & 15))];
            float4 kb = sK[(k1 << 4) | (i ^ (k1 & 15))];
            float4 qva = __ldg(&Q4[qoffA + i]);               // lane-uniform
            float4 qvb = __ldg(&Q4[qoffB + i]);
            dA0 += ka.x * qva.x + ka.y * qva.y + ka.z * qva.z + ka.w * qva.w;
            dA1 += kb.x * qva.x + kb.y * qva.y + kb.z * qva.z + kb.w * qva.w;
            dB0 += ka.x * qvb.x + ka.y * qvb.y + ka.z * qvb.z + ka.w * qvb.w;
            dB1 += kb.x * qvb.x + kb.y * qvb.y + kb.z * qvb.z + kb.w * qvb.w;
        }
        {
            float e0 = (k0 < nkA) ? __expf(dA0 * scale) : 0.f;
            float e1 = (k1 < nkA) ? __expf(dA1 * scale) : 0.f;
            sE[t0][k0] = e0;
            sE[t0][k1] = e1;
            float ls = e0 + e1;
            #pragma unroll
            for (int off = 16; off; off >>= 1)
                ls += __shfl_xor_sync(0xffffffffu, ls, off);
            if (lane == 0) g_pl[(bh * NT + t0) * NC + chunk] = ls;
        }
        if (hasB) {
            float e0 = (k0 < nkB) ? __expf(dB0 * scale) : 0.f;
            float e1 = (k1 < nkB) ? __expf(dB1 * scale) : 0.f;
            sE[tB][k0] = e0;
            sE[tB][k1] = e1;
            float ls = e0 + e1;
            #pragma unroll
            for (int off = 16; off; off >>= 1)
                ls += __shfl_xor_sync(0xffffffffu, ls, off);
            if (lane == 0) g_pl[(bh * NT + tB) * NC + chunk] = ls;
        }
    }
    __syncthreads();

    // ---- Phase B: 5 queries per warp; float4 e broadcasts; V conflict-free ----
    const float2* sV2 = (const float2*)sV;
    float acc[5][2];
    bool val[5];
    int tq[5];
    #pragma unroll
    for (int j = 0; j < 5; j++) {
        acc[j][0] = 0.f; acc[j][1] = 0.f;
        tq[j] = lo + w + 8 * j;
        val[j] = tq[j] < NT;
        if (!val[j]) tq[j] = lo;    // safe row; result discarded
    }
    for (int k4 = 0; k4 < KC / 4; k4++) {
        float ea[5][4];
        #pragma unroll
        for (int j = 0; j < 5; j++) {
            float4 ef = *(const float4*)&sE[tq[j]][k4 * 4];
            ea[j][0] = ef.x; ea[j][1] = ef.y; ea[j][2] = ef.z; ea[j][3] = ef.w;
        }
        #pragma unroll
        for (int kk = 0; kk < 4; kk++) {
            float2 v = sV2[(k4 * 4 + kk) * 32 + lane];
            #pragma unroll
            for (int j = 0; j < 5; j++) {
                acc[j][0] += ea[j][kk] * v.x;
                acc[j][1] += ea[j][kk] * v.y;
            }
        }
    }
    #pragma unroll
    for (int j = 0; j < 5; j++) {
        if (val[j]) {
            float* pa = &g_pacc[((size_t)(bh * NT + tq[j]) * NC + chunk) * D];
            pa[2 * lane]     = acc[j][0];
            pa[2 * lane + 1] = acc[j][1];
        }
    }
}

// ---------------- attention merge: 4 chunk-stripes x 64 dims, smem combine ------
__global__ void k_attn_merge(float* __restrict__ out) {
    int u = blockIdx.x;                 // (bh, sidx)
    int bh = u / NT, sidx = u % NT;
    int b = bh >> 3, h = bh & 7;
    int q = g_top[bh * NT + sidx];
    int tid = threadIdx.x;              // 256 threads
    int d = tid & 63, st = tid >> 6;    // 4 chunk-stripes
    int nch = (q >> 6) + 1;             // chunks [0, nch) were written

    float den = 0.f, num = 0.f;
    // unroll-by-2 over this stripe's chunks for extra MLP
    int ch = st;
    for (; ch + 4 < nch; ch += 8) {
        float l0 = __ldg(&g_pl[u * NC + ch]);
        float l1 = __ldg(&g_pl[u * NC + ch + 4]);
        float n0 = __ldg(&g_pacc[((size_t)u * NC + ch) * D + d]);
        float n1 = __ldg(&g_pacc[((size_t)u * NC + ch + 4) * D + d]);
        den += l0 + l1;
        num += n0 + n1;
    }
    if (ch < nch) {
        den += __ldg(&g_pl[u * NC + ch]);
        num += __ldg(&g_pacc[((size_t)u * NC + ch) * D + d]);
    }

    __shared__ float snum[4][64];
    __shared__ float sden[4];
    snum[st][d] = num;
    if (d == 0) sden[st] = den;
    __syncthreads();

    if (tid < 64) {
        float nn = snum[0][tid] + snum[1][tid] + snum[2][tid] + snum[3][tid];
        float dd = sden[0] + sden[1] + sden[2] + sden[3];
        out[(((size_t)b * L + q) * H + h) * D + tid] = nn / dd;
    }
}

// ---------------- launch ----------------
extern "C" void kernel_launch(void* const* d_in, const int* in_sizes, int n_in,
                              void* d_out, int out_size) {
    (void)in_sizes; (void)n_in; (void)out_size;
    const float* Q = (const float*)d_in[0];
    const float* K = (const float*)d_in[1];
    const float* V = (const float*)d_in[2];
    float* out = (float*)d_out;

    k_fused_M_csum<<<8192 + 1024, 256>>>(Q, K, V);
    k_fused_topk_scan<<<BH + 1024, 256>>>(V, out);
    k_attn_part<<<dim3(BH, NC), 256>>>(Q, K, V);
    k_attn_merge<<<BH * NT, 256>>>(out);
}